// round 1
// baseline (speedup 1.0000x reference)
#include <cuda_runtime.h>
#include <cstddef>

#define NR 2048
#define NC 32
#define NO 32
#define NI 32
#define NB 64
#define NCO (NC*NO)        // 1024
#define RSTRIDE (NCO*NB)   // 65536 floats per route in u_hat

// Scratch (device globals: allocation-free contract)
__device__ float g_uhat[(size_t)NR * NCO * NB];  // [r][c][o][b]  512 MB
__device__ float g_blog[NR * NC];                // routing logits b_ij [r][c]
__device__ float g_cij[NR * NC];                 // softmax(b_ij) over r
__device__ float g_v2[NCO * NB];                 // v in [c][o][b] layout

__device__ __forceinline__ unsigned long long fma2(unsigned long long a,
                                                   unsigned long long b,
                                                   unsigned long long c) {
    unsigned long long d;
    asm("fma.rn.f32x2 %0, %1, %2, %3;" : "=l"(d) : "l"(a), "l"(b), "l"(c));
    return d;
}

// ---------------------------------------------------------------------------
// Zero the routing logits (b_ij = 0) at the start of every launch.
__global__ void k_zero() {
    int i = blockIdx.x * blockDim.x + threadIdx.x;
    if (i < NR * NC) g_blog[i] = 0.f;
}

// ---------------------------------------------------------------------------
// u_hat[r][co][b] = dot(W[r,co,:], x[b,r,:])  — one block per route r.
// Each thread owns one b; i-dimension packed in f32x2 (2x fp32 FMA rate).
// W rows staged via SMEM (broadcast LDS.128), x row held in registers.
__global__ void __launch_bounds__(256) k_uhat(const float* __restrict__ x,
                                              const float* __restrict__ W) {
    __shared__ __align__(16) float ws[128 * NI];  // 16 KB chunk of W[r]
    const int r   = blockIdx.x;
    const int tid = threadIdx.x;
    const int b   = tid & 63;   // batch index
    const int g   = tid >> 6;   // row group 0..3

    // Load x[b, r, :] (32 floats, contiguous) packed as 16 x f32x2.
    unsigned long long xq[16];
    const unsigned long long* xp =
        (const unsigned long long*)(x + (size_t)b * (NR * NI) + (size_t)r * NI);
#pragma unroll
    for (int j = 0; j < 16; ++j) xq[j] = xp[j];

    for (int chunk = 0; chunk < 8; ++chunk) {
        // Stage 128 W rows (co = chunk*128 .. +127) into SMEM.
        const float4* wsrc =
            (const float4*)(W + (size_t)r * (NC * NO * NI) + (size_t)chunk * 4096);
        float4* wdst = (float4*)ws;
#pragma unroll
        for (int j = 0; j < 4; ++j) wdst[tid + j * 256] = wsrc[tid + j * 256];
        __syncthreads();

#pragma unroll 2
        for (int k = 0; k < 32; ++k) {
            const int row = g + (k << 2);
            const ulonglong2* wr = (const ulonglong2*)(ws + row * NI);
            unsigned long long a0 = 0ULL, a1 = 0ULL;
#pragma unroll
            for (int j = 0; j < 8; ++j) {
                ulonglong2 wv = wr[j];            // broadcast LDS.128
                a0 = fma2(wv.x, xq[2 * j], a0);
                a1 = fma2(wv.y, xq[2 * j + 1], a1);
            }
            float l0, h0, l1, h1;
            asm("mov.b64 {%0,%1}, %2;" : "=f"(l0), "=f"(h0) : "l"(a0));
            asm("mov.b64 {%0,%1}, %2;" : "=f"(l1), "=f"(h1) : "l"(a1));
            const int co = (chunk << 7) + row;
            g_uhat[(size_t)r * RSTRIDE + (size_t)co * NB + b] = (l0 + h0) + (l1 + h1);
        }
        __syncthreads();
    }
}

// ---------------------------------------------------------------------------
// c_ij[:, c] = softmax over r of b_ij[:, c]. One block per capsule c.
__global__ void __launch_bounds__(256) k_softmax() {
    const int c   = blockIdx.x;
    const int tid = threadIdx.x;
    __shared__ float sm[8];

    float vals[8];
#pragma unroll
    for (int j = 0; j < 8; ++j) vals[j] = g_blog[(tid + j * 256) * NC + c];

    float m = vals[0];
#pragma unroll
    for (int j = 1; j < 8; ++j) m = fmaxf(m, vals[j]);
#pragma unroll
    for (int off = 16; off; off >>= 1) m = fmaxf(m, __shfl_xor_sync(0xffffffffu, m, off));
    if ((tid & 31) == 0) sm[tid >> 5] = m;
    __syncthreads();
    float mm = sm[0];
#pragma unroll
    for (int j = 1; j < 8; ++j) mm = fmaxf(mm, sm[j]);
    __syncthreads();

    float e[8];
    float s = 0.f;
#pragma unroll
    for (int j = 0; j < 8; ++j) { e[j] = expf(vals[j] - mm); s += e[j]; }
#pragma unroll
    for (int off = 16; off; off >>= 1) s += __shfl_xor_sync(0xffffffffu, s, off);
    if ((tid & 31) == 0) sm[tid >> 5] = s;
    __syncthreads();
    float tot = 0.f;
#pragma unroll
    for (int j = 0; j < 8; ++j) tot += sm[j];
    const float inv = 1.f / tot;
#pragma unroll
    for (int j = 0; j < 8; ++j) g_cij[(tid + j * 256) * NC + c] = e[j] * inv;
}

// ---------------------------------------------------------------------------
// s[b,c,o] = sum_r c_ij[r,c] * u_hat[r][co][b]; v = squash(s).
// One block per co = c*32+o. Threads: b = tid&63, r-segment = tid>>6.
__global__ void __launch_bounds__(256) k_s(float* __restrict__ outp) {
    const int co  = blockIdx.x;
    const int c   = co >> 5;
    const int tid = threadIdx.x;
    __shared__ float cs[NR];
    __shared__ float red[4][64];

#pragma unroll
    for (int j = 0; j < 8; ++j) cs[tid + j * 256] = g_cij[(tid + j * 256) * NC + c];
    __syncthreads();

    const int b   = tid & 63;
    const int seg = tid >> 6;
    const float* p = g_uhat + (size_t)(seg * 512) * RSTRIDE + (size_t)co * NB + b;
    const int rbase = seg * 512;

    float acc = 0.f;
#pragma unroll 8
    for (int k = 0; k < 512; ++k) {
        acc = fmaf(cs[rbase + k], p[(size_t)k * RSTRIDE], acc);
    }
    red[seg][b] = acc;
    __syncthreads();

    if (seg == 0) {
        const float s  = (red[0][b] + red[1][b]) + (red[2][b] + red[3][b]);
        const float sq = s * s;
        const float v  = sq * s / ((1.f + sq) * sqrtf(sq));
        g_v2[co * NB + b] = v;                // [c][o][b] for the a-pass
        if (outp) outp[b * NCO + co] = v;     // [b][c][o][1] final output
    }
}

// ---------------------------------------------------------------------------
// b_ij[r,c] += (1/B) * sum_{b,o} u_hat[r][c][o][b] * v[c][o][b].
// One block per route r; warp w handles capsules {w, w+8, w+16, w+24}.
__global__ void __launch_bounds__(256) k_a() {
    const int r    = blockIdx.x;
    const int warp = threadIdx.x >> 5;
    const int lane = threadIdx.x & 31;

#pragma unroll
    for (int cc = 0; cc < 4; ++cc) {
        const int c = warp + cc * 8;
        const float4* up = (const float4*)(g_uhat + (size_t)r * RSTRIDE + c * (NO * NB));
        const float4* vp = (const float4*)(g_v2 + c * (NO * NB));
        float p = 0.f;
#pragma unroll
        for (int k = 0; k < 16; ++k) {
            const float4 u = up[lane + k * 32];
            const float4 v = vp[lane + k * 32];
            p += u.x * v.x + u.y * v.y + u.z * v.z + u.w * v.w;
        }
#pragma unroll
        for (int off = 16; off; off >>= 1) p += __shfl_xor_sync(0xffffffffu, p, off);
        if (lane == 0) g_blog[r * NC + c] += p * (1.f / NB);
    }
}

// ---------------------------------------------------------------------------
extern "C" void kernel_launch(void* const* d_in, const int* in_sizes, int n_in,
                              void* d_out, int out_size) {
    const float* x = (const float*)d_in[0];  // [B, R, I]  4,194,304 elems
    const float* W = (const float*)d_in[1];  // [R, C, O, I] 67,108,864 elems
    if (n_in >= 2 && in_sizes[0] > in_sizes[1]) {  // robust to input ordering
        const float* t = x; x = W; W = t;
    }
    float* out = (float*)d_out;

    k_zero<<<64, 1024>>>();
    k_uhat<<<NR, 256>>>(x, W);
    for (int it = 0; it < 3; ++it) {
        k_softmax<<<NC, 256>>>();
        k_s<<<NCO, 256>>>(it == 2 ? out : nullptr);
        if (it < 2) k_a<<<NR, 256>>>();
    }
}

// round 2
// speedup vs baseline: 1.0004x; 1.0004x over previous
#include <cuda_runtime.h>
#include <cstddef>

#define NR 2048
#define NC 32
#define NO 32
#define NI 32
#define NB 64
#define NCO (NC*NO)        // 1024
#define RSTRIDE (NCO*NB)   // 65536 floats per route in u_hat

// Scratch (device globals: allocation-free contract)
__device__ float g_uhat[(size_t)NR * NCO * NB];  // [r][c][o][b]  512 MB
__device__ float g_blog[NR * NC];                // routing logits b_ij [r][c]
__device__ float g_cij[NR * NC];                 // softmax(b_ij) over r
__device__ float g_v2[NCO * NB];                 // v in [c][o][b] layout

__device__ __forceinline__ unsigned long long fma2(unsigned long long a,
                                                   unsigned long long b,
                                                   unsigned long long c) {
    unsigned long long d;
    asm("fma.rn.f32x2 %0, %1, %2, %3;" : "=l"(d) : "l"(a), "l"(b), "l"(c));
    return d;
}

// ---------------------------------------------------------------------------
// Zero the routing logits (b_ij = 0) at the start of every launch.
__global__ void k_zero() {
    int i = blockIdx.x * blockDim.x + threadIdx.x;
    if (i < NR * NC) g_blog[i] = 0.f;
}

// ---------------------------------------------------------------------------
// u_hat[r][co][b] = dot(W[r,co,:], x[b,r,:])  — one block per route r.
// Each thread owns one b; i-dimension packed in f32x2 (2x fp32 FMA rate).
// W rows staged via SMEM (broadcast LDS.128), x row held in registers.
__global__ void __launch_bounds__(256) k_uhat(const float* __restrict__ x,
                                              const float* __restrict__ W) {
    __shared__ __align__(16) float ws[128 * NI];  // 16 KB chunk of W[r]
    const int r   = blockIdx.x;
    const int tid = threadIdx.x;
    const int b   = tid & 63;   // batch index
    const int g   = tid >> 6;   // row group 0..3

    // Load x[b, r, :] (32 floats, contiguous) packed as 16 x f32x2.
    unsigned long long xq[16];
    const unsigned long long* xp =
        (const unsigned long long*)(x + (size_t)b * (NR * NI) + (size_t)r * NI);
#pragma unroll
    for (int j = 0; j < 16; ++j) xq[j] = xp[j];

    for (int chunk = 0; chunk < 8; ++chunk) {
        // Stage 128 W rows (co = chunk*128 .. +127) into SMEM.
        const float4* wsrc =
            (const float4*)(W + (size_t)r * (NC * NO * NI) + (size_t)chunk * 4096);
        float4* wdst = (float4*)ws;
#pragma unroll
        for (int j = 0; j < 4; ++j) wdst[tid + j * 256] = wsrc[tid + j * 256];
        __syncthreads();

#pragma unroll 2
        for (int k = 0; k < 32; ++k) {
            const int row = g + (k << 2);
            const ulonglong2* wr = (const ulonglong2*)(ws + row * NI);
            unsigned long long a0 = 0ULL, a1 = 0ULL;
#pragma unroll
            for (int j = 0; j < 8; ++j) {
                ulonglong2 wv = wr[j];            // broadcast LDS.128
                a0 = fma2(wv.x, xq[2 * j], a0);
                a1 = fma2(wv.y, xq[2 * j + 1], a1);
            }
            float l0, h0, l1, h1;
            asm("mov.b64 {%0,%1}, %2;" : "=f"(l0), "=f"(h0) : "l"(a0));
            asm("mov.b64 {%0,%1}, %2;" : "=f"(l1), "=f"(h1) : "l"(a1));
            const int co = (chunk << 7) + row;
            g_uhat[(size_t)r * RSTRIDE + (size_t)co * NB + b] = (l0 + h0) + (l1 + h1);
        }
        __syncthreads();
    }
}

// ---------------------------------------------------------------------------
// c_ij[:, c] = softmax over r of b_ij[:, c]. One block per capsule c.
__global__ void __launch_bounds__(256) k_softmax() {
    const int c   = blockIdx.x;
    const int tid = threadIdx.x;
    __shared__ float sm[8];

    float vals[8];
#pragma unroll
    for (int j = 0; j < 8; ++j) vals[j] = g_blog[(tid + j * 256) * NC + c];

    float m = vals[0];
#pragma unroll
    for (int j = 1; j < 8; ++j) m = fmaxf(m, vals[j]);
#pragma unroll
    for (int off = 16; off; off >>= 1) m = fmaxf(m, __shfl_xor_sync(0xffffffffu, m, off));
    if ((tid & 31) == 0) sm[tid >> 5] = m;
    __syncthreads();
    float mm = sm[0];
#pragma unroll
    for (int j = 1; j < 8; ++j) mm = fmaxf(mm, sm[j]);
    __syncthreads();

    float e[8];
    float s = 0.f;
#pragma unroll
    for (int j = 0; j < 8; ++j) { e[j] = expf(vals[j] - mm); s += e[j]; }
#pragma unroll
    for (int off = 16; off; off >>= 1) s += __shfl_xor_sync(0xffffffffu, s, off);
    if ((tid & 31) == 0) sm[tid >> 5] = s;
    __syncthreads();
    float tot = 0.f;
#pragma unroll
    for (int j = 0; j < 8; ++j) tot += sm[j];
    const float inv = 1.f / tot;
#pragma unroll
    for (int j = 0; j < 8; ++j) g_cij[(tid + j * 256) * NC + c] = e[j] * inv;
}

// ---------------------------------------------------------------------------
// s[b,c,o] = sum_r c_ij[r,c] * u_hat[r][co][b]; v = squash(s).
// One block per co = c*32+o. Threads: b = tid&63, r-segment = tid>>6.
__global__ void __launch_bounds__(256) k_s(float* __restrict__ outp) {
    const int co  = blockIdx.x;
    const int c   = co >> 5;
    const int tid = threadIdx.x;
    __shared__ float cs[NR];
    __shared__ float red[4][64];

#pragma unroll
    for (int j = 0; j < 8; ++j) cs[tid + j * 256] = g_cij[(tid + j * 256) * NC + c];
    __syncthreads();

    const int b   = tid & 63;
    const int seg = tid >> 6;
    const float* p = g_uhat + (size_t)(seg * 512) * RSTRIDE + (size_t)co * NB + b;
    const int rbase = seg * 512;

    float acc = 0.f;
#pragma unroll 8
    for (int k = 0; k < 512; ++k) {
        acc = fmaf(cs[rbase + k], p[(size_t)k * RSTRIDE], acc);
    }
    red[seg][b] = acc;
    __syncthreads();

    if (seg == 0) {
        const float s  = (red[0][b] + red[1][b]) + (red[2][b] + red[3][b]);
        const float sq = s * s;
        const float v  = sq * s / ((1.f + sq) * sqrtf(sq));
        g_v2[co * NB + b] = v;                // [c][o][b] for the a-pass
        if (outp) outp[b * NCO + co] = v;     // [b][c][o][1] final output
    }
}

// ---------------------------------------------------------------------------
// b_ij[r,c] += (1/B) * sum_{b,o} u_hat[r][c][o][b] * v[c][o][b].
// One block per route r; warp w handles capsules {w, w+8, w+16, w+24}.
__global__ void __launch_bounds__(256) k_a() {
    const int r    = blockIdx.x;
    const int warp = threadIdx.x >> 5;
    const int lane = threadIdx.x & 31;

#pragma unroll
    for (int cc = 0; cc < 4; ++cc) {
        const int c = warp + cc * 8;
        const float4* up = (const float4*)(g_uhat + (size_t)r * RSTRIDE + c * (NO * NB));
        const float4* vp = (const float4*)(g_v2 + c * (NO * NB));
        float p = 0.f;
#pragma unroll
        for (int k = 0; k < 16; ++k) {
            const float4 u = up[lane + k * 32];
            const float4 v = vp[lane + k * 32];
            p += u.x * v.x + u.y * v.y + u.z * v.z + u.w * v.w;
        }
#pragma unroll
        for (int off = 16; off; off >>= 1) p += __shfl_xor_sync(0xffffffffu, p, off);
        if (lane == 0) g_blog[r * NC + c] += p * (1.f / NB);
    }
}

// ---------------------------------------------------------------------------
extern "C" void kernel_launch(void* const* d_in, const int* in_sizes, int n_in,
                              void* d_out, int out_size) {
    const float* x = (const float*)d_in[0];  // [B, R, I]  4,194,304 elems
    const float* W = (const float*)d_in[1];  // [R, C, O, I] 67,108,864 elems
    if (n_in >= 2 && in_sizes[0] > in_sizes[1]) {  // robust to input ordering
        const float* t = x; x = W; W = t;
    }
    float* out = (float*)d_out;

    k_zero<<<64, 1024>>>();
    k_uhat<<<NR, 256>>>(x, W);
    for (int it = 0; it < 3; ++it) {
        k_softmax<<<NC, 256>>>();
        k_s<<<NCO, 256>>>(it == 2 ? out : nullptr);
        if (it < 2) k_a<<<NR, 256>>>();
    }
}

// round 3
// speedup vs baseline: 1.3525x; 1.3520x over previous
#include <cuda_runtime.h>
#include <cuda_fp16.h>
#include <cstddef>

#define NR 2048
#define NC 32
#define NO 32
#define NI 32
#define NB 64
#define NCO (NC*NO)        // 1024
#define RSTRIDE (NCO*NB)   // 65536 elements per route in u_hat

// Scratch (device globals: allocation-free contract)
__device__ __half g_uhat[(size_t)NR * NCO * NB]; // [r][c][o][b]  268 MB fp16
__device__ float  g_blog[NR * NC];               // routing logits b_ij [r][c]
__device__ float  g_cij[NR * NC];                // softmax(b_ij) over r
__device__ float  g_v2[NCO * NB];                // v in [c][o][b] layout

__device__ __forceinline__ unsigned long long fma2(unsigned long long a,
                                                   unsigned long long b,
                                                   unsigned long long c) {
    unsigned long long d;
    asm("fma.rn.f32x2 %0, %1, %2, %3;" : "=l"(d) : "l"(a), "l"(b), "l"(c));
    return d;
}

// ---------------------------------------------------------------------------
__global__ void k_zero() {
    int i = blockIdx.x * blockDim.x + threadIdx.x;
    if (i < NR * NC) g_blog[i] = 0.f;
}

// ---------------------------------------------------------------------------
// u_hat[r][co][b] = dot(W[r,co,:], x[b,r,:]) — one block per route r.
// Thread owns one b; i packed in f32x2; W staged via SMEM broadcast LDS.128.
// Output stored as fp16 (halves store traffic).
__global__ void __launch_bounds__(256) k_uhat(const float* __restrict__ x,
                                              const float* __restrict__ W) {
    __shared__ __align__(16) float ws[128 * NI];  // 16 KB chunk of W[r]
    const int r   = blockIdx.x;
    const int tid = threadIdx.x;
    const int b   = tid & 63;   // batch index
    const int g   = tid >> 6;   // row group 0..3

    unsigned long long xq[16];
    const unsigned long long* xp =
        (const unsigned long long*)(x + (size_t)b * (NR * NI) + (size_t)r * NI);
#pragma unroll
    for (int j = 0; j < 16; ++j) xq[j] = xp[j];

    for (int chunk = 0; chunk < 8; ++chunk) {
        const float4* wsrc =
            (const float4*)(W + (size_t)r * (NC * NO * NI) + (size_t)chunk * 4096);
        float4* wdst = (float4*)ws;
#pragma unroll
        for (int j = 0; j < 4; ++j) wdst[tid + j * 256] = wsrc[tid + j * 256];
        __syncthreads();

#pragma unroll 2
        for (int k = 0; k < 32; ++k) {
            const int row = g + (k << 2);
            const ulonglong2* wr = (const ulonglong2*)(ws + row * NI);
            unsigned long long a0 = 0ULL, a1 = 0ULL;
#pragma unroll
            for (int j = 0; j < 8; ++j) {
                ulonglong2 wv = wr[j];            // broadcast LDS.128
                a0 = fma2(wv.x, xq[2 * j], a0);
                a1 = fma2(wv.y, xq[2 * j + 1], a1);
            }
            float l0, h0, l1, h1;
            asm("mov.b64 {%0,%1}, %2;" : "=f"(l0), "=f"(h0) : "l"(a0));
            asm("mov.b64 {%0,%1}, %2;" : "=f"(l1), "=f"(h1) : "l"(a1));
            const int co = (chunk << 7) + row;
            g_uhat[(size_t)r * RSTRIDE + (size_t)co * NB + b] =
                __float2half_rn((l0 + h0) + (l1 + h1));
        }
        __syncthreads();
    }
}

// ---------------------------------------------------------------------------
// c_ij[:, c] = softmax over r of b_ij[:, c]. One block per capsule c.
__global__ void __launch_bounds__(256) k_softmax() {
    const int c   = blockIdx.x;
    const int tid = threadIdx.x;
    __shared__ float sm[8];

    float vals[8];
#pragma unroll
    for (int j = 0; j < 8; ++j) vals[j] = g_blog[(tid + j * 256) * NC + c];

    float m = vals[0];
#pragma unroll
    for (int j = 1; j < 8; ++j) m = fmaxf(m, vals[j]);
#pragma unroll
    for (int off = 16; off; off >>= 1) m = fmaxf(m, __shfl_xor_sync(0xffffffffu, m, off));
    if ((tid & 31) == 0) sm[tid >> 5] = m;
    __syncthreads();
    float mm = sm[0];
#pragma unroll
    for (int j = 1; j < 8; ++j) mm = fmaxf(mm, sm[j]);
    __syncthreads();

    float e[8];
    float s = 0.f;
#pragma unroll
    for (int j = 0; j < 8; ++j) { e[j] = expf(vals[j] - mm); s += e[j]; }
#pragma unroll
    for (int off = 16; off; off >>= 1) s += __shfl_xor_sync(0xffffffffu, s, off);
    if ((tid & 31) == 0) sm[tid >> 5] = s;
    __syncthreads();
    float tot = 0.f;
#pragma unroll
    for (int j = 0; j < 8; ++j) tot += sm[j];
    const float inv = 1.f / tot;
#pragma unroll
    for (int j = 0; j < 8; ++j) g_cij[(tid + j * 256) * NC + c] = e[j] * inv;
}

// ---------------------------------------------------------------------------
// s[b,c,o] = sum_r c_ij[r,c] * u_hat[r][co][b]; v = squash(s).
// One block per co. Thread owns a b-pair (half2), seg = 1/8 of routes.
__global__ void __launch_bounds__(256) k_s(float* __restrict__ outp) {
    const int co  = blockIdx.x;
    const int c   = co >> 5;
    const int tid = threadIdx.x;
    __shared__ float cs[NR];
    __shared__ float red[8][64];

#pragma unroll
    for (int j = 0; j < 8; ++j) cs[tid + j * 256] = g_cij[(tid + j * 256) * NC + c];
    __syncthreads();

    const int bp  = tid & 31;   // b-pair index (covers b = 2bp, 2bp+1)
    const int seg = tid >> 5;   // 8 segments of 256 routes
    const __half2* p =
        (const __half2*)(g_uhat + (size_t)(seg * 256) * RSTRIDE + (size_t)co * NB) + bp;
    const int rbase = seg * 256;

    float ax = 0.f, ay = 0.f;
#pragma unroll 8
    for (int k = 0; k < 256; ++k) {
        const float2 f = __half22float2(p[(size_t)k * (RSTRIDE / 2)]);
        const float cc = cs[rbase + k];
        ax = fmaf(cc, f.x, ax);
        ay = fmaf(cc, f.y, ay);
    }
    red[seg][2 * bp]     = ax;
    red[seg][2 * bp + 1] = ay;
    __syncthreads();

    if (tid < 64) {
        float s = 0.f;
#pragma unroll
        for (int j = 0; j < 8; ++j) s += red[j][tid];
        const float sq = s * s;
        const float v  = sq * s / ((1.f + sq) * sqrtf(sq));
        g_v2[co * NB + tid] = v;                 // [c][o][b] for the a-pass
        if (outp) outp[tid * NCO + co] = v;      // [b][c][o][1] final output
    }
}

// ---------------------------------------------------------------------------
// b_ij[r,c] += (1/B) * sum_{b,o} u_hat[r][c][o][b] * v[c][o][b].
// Grid: (route-group of 32, capsule c). v[c] staged in SMEM then registers,
// so v generates ~16 MB of L2 traffic total instead of 512 MB.
__global__ void __launch_bounds__(256) k_a() {
    const int c    = blockIdx.y;
    const int r0   = blockIdx.x * 32;
    const int tid  = threadIdx.x;
    const int lane = tid & 31;
    const int w    = tid >> 5;
    __shared__ __align__(16) float vsm[NO * NB];  // 8 KB

    const float4* vsrc = (const float4*)(g_v2 + c * (NO * NB));
    float4* vdst = (float4*)vsm;
#pragma unroll
    for (int j = 0; j < 2; ++j) vdst[tid + j * 256] = vsrc[tid + j * 256];
    __syncthreads();

    float4 vr[16];
#pragma unroll
    for (int k = 0; k < 8; ++k) {
        vr[2 * k]     = ((const float4*)vsm)[2 * (lane + k * 32)];
        vr[2 * k + 1] = ((const float4*)vsm)[2 * (lane + k * 32) + 1];
    }

#pragma unroll
    for (int i = 0; i < 4; ++i) {
        const int r = r0 + w * 4 + i;
        const uint4* up = (const uint4*)(g_uhat + (size_t)r * RSTRIDE + c * (NO * NB));
        float p = 0.f;
#pragma unroll
        for (int k = 0; k < 8; ++k) {
            const uint4 u = up[lane + k * 32];
            const float2 f0 = __half22float2(*(const __half2*)&u.x);
            const float2 f1 = __half22float2(*(const __half2*)&u.y);
            const float2 f2 = __half22float2(*(const __half2*)&u.z);
            const float2 f3 = __half22float2(*(const __half2*)&u.w);
            const float4 v0 = vr[2 * k];
            const float4 v1 = vr[2 * k + 1];
            p = fmaf(f0.x, v0.x, p); p = fmaf(f0.y, v0.y, p);
            p = fmaf(f1.x, v0.z, p); p = fmaf(f1.y, v0.w, p);
            p = fmaf(f2.x, v1.x, p); p = fmaf(f2.y, v1.y, p);
            p = fmaf(f3.x, v1.z, p); p = fmaf(f3.y, v1.w, p);
        }
#pragma unroll
        for (int off = 16; off; off >>= 1) p += __shfl_xor_sync(0xffffffffu, p, off);
        if (lane == 0) g_blog[r * NC + c] += p * (1.f / NB);
    }
}

// ---------------------------------------------------------------------------
extern "C" void kernel_launch(void* const* d_in, const int* in_sizes, int n_in,
                              void* d_out, int out_size) {
    const float* x = (const float*)d_in[0];  // [B, R, I]
    const float* W = (const float*)d_in[1];  // [R, C, O, I]
    if (n_in >= 2 && in_sizes[0] > in_sizes[1]) {  // robust to input ordering
        const float* t = x; x = W; W = t;
    }
    float* out = (float*)d_out;

    k_zero<<<64, 1024>>>();
    k_uhat<<<NR, 256>>>(x, W);
    for (int it = 0; it < 3; ++it) {
        k_softmax<<<NC, 256>>>();
        k_s<<<NCO, 256>>>(it == 2 ? out : nullptr);
        if (it < 2) k_a<<<dim3(64, 32), 256>>>();
    }
}

// round 5
// speedup vs baseline: 1.8888x; 1.3965x over previous
#include <cuda_runtime.h>
#include <cuda_fp16.h>
#include <cuda_bf16.h>
#include <cstdint>
#include <cstddef>

#define NR 2048
#define NC 32
#define NO 32
#define NI 32
#define NB 64
#define NCO (NC*NO)        // 1024
#define RSTRIDE (NCO*NB)   // 65536 elements per route in u_hat

// Scratch (device globals: allocation-free contract)
__device__ __half g_uhat[(size_t)NR * NCO * NB]; // [r][c][o][b]  268 MB fp16
__device__ float  g_blog[NR * NC];               // routing logits b_ij [r][c]
__device__ float  g_cij[NR * NC];                // softmax(b_ij) over r
__device__ float  g_v2[NCO * NB];                // v in [c][o][b] layout

// ---------------------------------------------------------------------------
// pack two fp32 -> bf16x2 (low half = a, high half = b)
__device__ __forceinline__ uint32_t pack_bf16x2(float a, float b) {
    uint32_t r;
    asm("cvt.rn.bf16x2.f32 %0, %1, %2;" : "=r"(r) : "f"(b), "f"(a));
    return r;
}
// split float2 into bf16x2 hi + bf16x2 residual (lo)
__device__ __forceinline__ void split2(float2 v, uint32_t& h, uint32_t& l) {
    h = pack_bf16x2(v.x, v.y);
    const float h0 = __uint_as_float(h << 16);
    const float h1 = __uint_as_float(h & 0xffff0000u);
    l = pack_bf16x2(v.x - h0, v.y - h1);
}
// D += A*B  (m16n8k16, bf16 in, fp32 acc) — plain mma.sync (no sm_103a features)
__device__ __forceinline__ void mma16816(float* c, const uint32_t* a,
                                         const uint32_t* b) {
    asm volatile(
        "mma.sync.aligned.m16n8k16.row.col.f32.bf16.bf16.f32 "
        "{%0,%1,%2,%3},{%4,%5,%6,%7},{%8,%9},{%0,%1,%2,%3};"
        : "+f"(c[0]), "+f"(c[1]), "+f"(c[2]), "+f"(c[3])
        : "r"(a[0]), "r"(a[1]), "r"(a[2]), "r"(a[3]), "r"(b[0]), "r"(b[1]));
}

// ---------------------------------------------------------------------------
__global__ void k_zero() {
    int i = blockIdx.x * blockDim.x + threadIdx.x;
    if (i < NR * NC) g_blog[i] = 0.f;
}

// ---------------------------------------------------------------------------
// u_hat via mma.sync: per route r, D[1024co x 64b] = W_r[1024x32] @ x_r^T.
// bf16 hi/lo split: D = Wh*Xh + Wh*Xl + Wl*Xh accumulated in fp32.
// Block = route r, 8 warps; warp w owns co rows [w*128, w*128+128) (8 m16 tiles).
// B (x_r) fragments held in registers for the whole block.
__global__ void __launch_bounds__(256) k_uhat(const float* __restrict__ x,
                                              const float* __restrict__ W) {
    const int r    = blockIdx.x;
    const int tid  = threadIdx.x;
    const int w    = tid >> 5;
    const int lane = tid & 31;
    const int g    = lane >> 2;   // group id 0..7
    const int tg   = lane & 3;    // thread-in-group

    // --- B fragments (x_r as k16 x n8, col-major): Bh/Bl[nt][kstep][reg]
    uint32_t Bh[8][2][2], Bl[8][2][2];
#pragma unroll
    for (int nt = 0; nt < 8; ++nt) {
        const float* xr = x + (size_t)(nt * 8 + g) * (NR * NI) + (size_t)r * NI;
#pragma unroll
        for (int ks = 0; ks < 2; ++ks) {
            const float2 v0 = *(const float2*)(xr + ks * 16 + 2 * tg);
            const float2 v1 = *(const float2*)(xr + ks * 16 + 2 * tg + 8);
            split2(v0, Bh[nt][ks][0], Bl[nt][ks][0]);
            split2(v1, Bh[nt][ks][1], Bl[nt][ks][1]);
        }
    }

    const float* wbase = W + (size_t)r * (NCO * NI);
    __half* const ubase = g_uhat + (size_t)r * RSTRIDE;

#pragma unroll 1
    for (int mt = 0; mt < 8; ++mt) {
        const int co0 = w * 128 + mt * 16 + g;      // rows g and g+8 of this tile
        const float* wr0 = wbase + (size_t)co0 * NI;
        const float* wr1 = wr0 + 8 * NI;

        // --- A fragments (W tile m16 x k16, row-major): Ah/Al[kstep][reg]
        uint32_t Ah[2][4], Al[2][4];
#pragma unroll
        for (int ks = 0; ks < 2; ++ks) {
            float2 v;
            v = *(const float2*)(wr0 + ks * 16 + 2 * tg);     split2(v, Ah[ks][0], Al[ks][0]);
            v = *(const float2*)(wr1 + ks * 16 + 2 * tg);     split2(v, Ah[ks][1], Al[ks][1]);
            v = *(const float2*)(wr0 + ks * 16 + 2 * tg + 8); split2(v, Ah[ks][2], Al[ks][2]);
            v = *(const float2*)(wr1 + ks * 16 + 2 * tg + 8); split2(v, Ah[ks][3], Al[ks][3]);
        }

#pragma unroll
        for (int nt = 0; nt < 8; ++nt) {
            float acc[4] = {0.f, 0.f, 0.f, 0.f};
#pragma unroll
            for (int ks = 0; ks < 2; ++ks) {
                mma16816(acc, Ah[ks], Bh[nt][ks]);
                mma16816(acc, Ah[ks], Bl[nt][ks]);
                mma16816(acc, Al[ks], Bh[nt][ks]);
            }
            const int b0 = nt * 8 + 2 * tg;
            *(__half2*)(ubase + (size_t)co0 * NB + b0) =
                __floats2half2_rn(acc[0], acc[1]);
            *(__half2*)(ubase + (size_t)(co0 + 8) * NB + b0) =
                __floats2half2_rn(acc[2], acc[3]);
        }
    }
}

// ---------------------------------------------------------------------------
// c_ij[:, c] = softmax over r of b_ij[:, c]. One block per capsule c.
__global__ void __launch_bounds__(256) k_softmax() {
    const int c   = blockIdx.x;
    const int tid = threadIdx.x;
    __shared__ float sm[8];

    float vals[8];
#pragma unroll
    for (int j = 0; j < 8; ++j) vals[j] = g_blog[(tid + j * 256) * NC + c];

    float m = vals[0];
#pragma unroll
    for (int j = 1; j < 8; ++j) m = fmaxf(m, vals[j]);
#pragma unroll
    for (int off = 16; off; off >>= 1) m = fmaxf(m, __shfl_xor_sync(0xffffffffu, m, off));
    if ((tid & 31) == 0) sm[tid >> 5] = m;
    __syncthreads();
    float mm = sm[0];
#pragma unroll
    for (int j = 1; j < 8; ++j) mm = fmaxf(mm, sm[j]);
    __syncthreads();

    float e[8];
    float s = 0.f;
#pragma unroll
    for (int j = 0; j < 8; ++j) { e[j] = expf(vals[j] - mm); s += e[j]; }
#pragma unroll
    for (int off = 16; off; off >>= 1) s += __shfl_xor_sync(0xffffffffu, s, off);
    if ((tid & 31) == 0) sm[tid >> 5] = s;
    __syncthreads();
    float tot = 0.f;
#pragma unroll
    for (int j = 0; j < 8; ++j) tot += sm[j];
    const float inv = 1.f / tot;
#pragma unroll
    for (int j = 0; j < 8; ++j) g_cij[(tid + j * 256) * NC + c] = e[j] * inv;
}

// ---------------------------------------------------------------------------
// s[b,c,o] = sum_r c_ij[r,c] * u_hat[r][co][b]; v = squash(s).
// One block per co-PAIR (wider 8B loads). warp = seg of 256 routes;
// lane: co_l = lane>>4, b-quad = (lane&15)*4.
__global__ void __launch_bounds__(256) k_s(float* __restrict__ outp) {
    const int co2 = blockIdx.x;          // 0..511, covers co = 2*co2, 2*co2+1
    const int c   = co2 >> 4;
    const int tid = threadIdx.x;
    __shared__ float cs[NR];
    __shared__ float red[8][128];

#pragma unroll
    for (int j = 0; j < 8; ++j) cs[tid + j * 256] = g_cij[(tid + j * 256) * NC + c];
    __syncthreads();

    const int seg  = tid >> 5;
    const int lane = tid & 31;
    const int co_l = lane >> 4;
    const int b4   = (lane & 15) * 4;
    const uint2* p = (const uint2*)(g_uhat + (size_t)(seg * 256) * RSTRIDE
                                    + (size_t)co2 * 128 + co_l * 64 + b4);
    const float* csp = cs + seg * 256;

    float a0 = 0.f, a1 = 0.f, a2 = 0.f, a3 = 0.f;
#pragma unroll 8
    for (int k = 0; k < 256; ++k) {
        const uint2 u = p[(size_t)k * (RSTRIDE / 4)];
        const float2 f0 = __half22float2(*(const __half2*)&u.x);
        const float2 f1 = __half22float2(*(const __half2*)&u.y);
        const float cc = csp[k];
        a0 = fmaf(cc, f0.x, a0);
        a1 = fmaf(cc, f0.y, a1);
        a2 = fmaf(cc, f1.x, a2);
        a3 = fmaf(cc, f1.y, a3);
    }
    red[seg][co_l * 64 + b4 + 0] = a0;
    red[seg][co_l * 64 + b4 + 1] = a1;
    red[seg][co_l * 64 + b4 + 2] = a2;
    red[seg][co_l * 64 + b4 + 3] = a3;
    __syncthreads();

    if (tid < 128) {
        float s = 0.f;
#pragma unroll
        for (int j = 0; j < 8; ++j) s += red[j][tid];
        const int co = co2 * 2 + (tid >> 6);
        const int b  = tid & 63;
        const float sq = s * s;
        const float v  = sq * s / ((1.f + sq) * sqrtf(sq));
        g_v2[co * NB + b] = v;                 // [c][o][b] for the a-pass
        if (outp) outp[b * NCO + co] = v;      // [b][c][o][1] final output
    }
}

// ---------------------------------------------------------------------------
// b_ij[r,c] += (1/B) * sum_{b,o} u_hat[r][c][o][b] * v[c][o][b].
__global__ void __launch_bounds__(256) k_a() {
    const int c    = blockIdx.y;
    const int r0   = blockIdx.x * 32;
    const int tid  = threadIdx.x;
    const int lane = tid & 31;
    const int w    = tid >> 5;
    __shared__ __align__(16) float vsm[NO * NB];  // 8 KB

    const float4* vsrc = (const float4*)(g_v2 + c * (NO * NB));
    float4* vdst = (float4*)vsm;
#pragma unroll
    for (int j = 0; j < 2; ++j) vdst[tid + j * 256] = vsrc[tid + j * 256];
    __syncthreads();

    float4 vr[16];
#pragma unroll
    for (int k = 0; k < 8; ++k) {
        vr[2 * k]     = ((const float4*)vsm)[2 * (lane + k * 32)];
        vr[2 * k + 1] = ((const float4*)vsm)[2 * (lane + k * 32) + 1];
    }

#pragma unroll
    for (int i = 0; i < 4; ++i) {
        const int r = r0 + w * 4 + i;
        const uint4* up = (const uint4*)(g_uhat + (size_t)r * RSTRIDE + c * (NO * NB));
        float p = 0.f;
#pragma unroll
        for (int k = 0; k < 8; ++k) {
            const uint4 u = up[lane + k * 32];
            const float2 f0 = __half22float2(*(const __half2*)&u.x);
            const float2 f1 = __half22float2(*(const __half2*)&u.y);
            const float2 f2 = __half22float2(*(const __half2*)&u.z);
            const float2 f3 = __half22float2(*(const __half2*)&u.w);
            const float4 v0 = vr[2 * k];
            const float4 v1 = vr[2 * k + 1];
            p = fmaf(f0.x, v0.x, p); p = fmaf(f0.y, v0.y, p);
            p = fmaf(f1.x, v0.z, p); p = fmaf(f1.y, v0.w, p);
            p = fmaf(f2.x, v1.x, p); p = fmaf(f2.y, v1.y, p);
            p = fmaf(f3.x, v1.z, p); p = fmaf(f3.y, v1.w, p);
        }
#pragma unroll
        for (int off = 16; off; off >>= 1) p += __shfl_xor_sync(0xffffffffu, p, off);
        if (lane == 0) g_blog[r * NC + c] += p * (1.f / NB);
    }
}

// ---------------------------------------------------------------------------
extern "C" void kernel_launch(void* const* d_in, const int* in_sizes, int n_in,
                              void* d_out, int out_size) {
    const float* x = (const float*)d_in[0];  // [B, R, I]
    const float* W = (const float*)d_in[1];  // [R, C, O, I]
    if (n_in >= 2 && in_sizes[0] > in_sizes[1]) {  // robust to input ordering
        const float* t = x; x = W; W = t;
    }
    float* out = (float*)d_out;

    k_zero<<<64, 1024>>>();
    k_uhat<<<NR, 256>>>(x, W);
    for (int it = 0; it < 3; ++it) {
        k_softmax<<<NC, 256>>>();
        k_s<<<512, 256>>>(it == 2 ? out : nullptr);
        if (it < 2) k_a<<<dim3(64, 32), 256>>>();
    }
}